// round 6
// baseline (speedup 1.0000x reference)
#include <cuda_runtime.h>
#include <cuda_bf16.h>

// Problem constants: B=2097152, C=3, T=5
#define B_TOTAL     2097152
#define TPB         256
#define WARPS_PB    (TPB / 32)                     // 8
#define NBLK        740                            // 5 blocks x 148 SMs, 1 wave
#define NWARP       (NBLK * WARPS_PB)              // 5920
#define WTILE_B     32                             // b per warp-tile (1 per lane)
#define NWTILES     (B_TOTAL / WTILE_B)            // 65536
#define PRED_C      120                            // float4 chunks per tile (32*15/4)
#define LAB_C       40                             // int4 chunks per tile (32*5/4)
#define TILE_C      (PRED_C + LAB_C)               // 160 chunks = 2560 B

#define FILLUP      (-100)
#define BASE_P      (0.2f / 3.0f)                  // SMOOTHING / C
#define ONE_MS      0.8f                           // 1 - SMOOTHING

__device__ float        g_partials[NBLK];
__device__ unsigned int g_done_count = 0;

__device__ __forceinline__ void cp16(void* smem_dst, const void* gmem_src)
{
    unsigned int saddr = (unsigned int)__cvta_generic_to_shared(smem_dst);
    asm volatile("cp.async.cg.shared.global [%0], [%1], 16;\n"
                 :: "r"(saddr), "l"(gmem_src));
}
__device__ __forceinline__ void cp_commit()
{
    asm volatile("cp.async.commit_group;\n" ::: "memory");
}
template <int N>
__device__ __forceinline__ void cp_wait()
{
    asm volatile("cp.async.wait_group %0;\n" :: "n"(N) : "memory");
}

// Per-lane prefetch of one warp-tile: exactly 5 16B chunks, no idle lanes.
// Chunk j in [0,120) comes from pred stream, j in [120,160) from label stream.
__device__ __forceinline__ void prefetch_wtile(char* sbuf, int lane, long tile,
                                               const float4* __restrict__ pred4,
                                               const int4* __restrict__ lab4)
{
    const float4* gp = pred4 + tile * PRED_C;
    const int4*   gl = lab4  + tile * LAB_C;
#pragma unroll
    for (int k = 0; k < 5; ++k) {
        int j = lane + k * 32;
        const void* src = (j < PRED_C) ? (const void*)(gp + j)
                                       : (const void*)(gl + (j - PRED_C));
        cp16(sbuf + j * 16, src);
    }
}

__global__ __launch_bounds__(TPB, 5)
void ce_lsr_warp_pipe_kernel(const float* __restrict__ pred,
                             const int* __restrict__ lab,
                             float* __restrict__ out)
{
    // Per-warp private double buffers: [warp][buf][160 chunks of 16B]
    __shared__ float4 s_buf[WARPS_PB][2][TILE_C];
    __shared__ float  s_red[WARPS_PB];
    __shared__ bool   s_is_last;

    const int tid  = threadIdx.x;
    const int wid  = tid >> 5;
    const int lane = tid & 31;
    const int gw   = blockIdx.x * WARPS_PB + wid;    // global warp id

    const float4* pred4 = reinterpret_cast<const float4*>(pred);
    const int4*   lab4  = reinterpret_cast<const int4*>(lab);

    char* buf0 = reinterpret_cast<char*>(s_buf[wid][0]);
    char* buf1 = reinterpret_cast<char*>(s_buf[wid][1]);

    float acc = 0.0f;

    // Warp-private pipeline over tiles gw, gw+NWARP, gw+2*NWARP, ...
    long t = gw;
    if (t < NWTILES) {
        prefetch_wtile(buf0, lane, t, pred4, lab4);
        cp_commit();
        long tn = t + NWARP;
        if (tn < NWTILES) {
            prefetch_wtile(buf1, lane, tn, pred4, lab4);
            cp_commit();
        }

        int buf = 0;
        for (; t < NWTILES; t += NWARP) {
            long t2 = t + 2 * (long)NWARP;
            if (t + NWARP < NWTILES) cp_wait<1>();   // current tile's group done
            else                     cp_wait<0>();
            __syncwarp();

            char* cb = buf ? buf1 : buf0;
            // Lane's 15 pred floats: word stride 15, coprime with 32 -> no conflicts
            const float* x  = reinterpret_cast<const float*>(cb) + lane * 15;
            const int*   lb = reinterpret_cast<const int*>(cb + PRED_C * 16) + lane * 5;

#pragma unroll
            for (int tt = 0; tt < 5; ++tt) {
                float x0 = x[tt], x1 = x[5 + tt], x2 = x[10 + tt];
                int   l  = lb[tt];

                // lse = x0 + log(1 + e^(x1-x0) + e^(x2-x0))  (2 exp + 1 log)
                float e   = 1.0f + __expf(x1 - x0) + __expf(x2 - x0);
                float lmx = __logf(e);

                float xl    = (l == 0) ? x0 : ((l == 1) ? x1 : x2);
                float valid = (l != FILLUP) ? 1.0f : 0.0f;

                // loss = lse - (S/C)*(x0+x1+x2) - (1-S)*x_label
                acc += valid * (x0 + lmx - BASE_P * (x0 + x1 + x2) - ONE_MS * xl);
            }
            __syncwarp();   // all lanes done reading before this buffer refills

            if (t2 < NWTILES) {
                prefetch_wtile(cb, lane, t2, pred4, lab4);
                cp_commit();
            }
            buf ^= 1;
        }
    }

    // ---- Deterministic reduction: warp -> block ----
#pragma unroll
    for (int o = 16; o > 0; o >>= 1)
        acc += __shfl_xor_sync(0xffffffffu, acc, o);
    if (lane == 0) s_red[wid] = acc;
    __syncthreads();

    if (tid == 0) {
        float p = 0.0f;
#pragma unroll
        for (int w = 0; w < WARPS_PB; ++w) p += s_red[w];
        g_partials[blockIdx.x] = p;
        __threadfence();
        unsigned int prev = atomicAdd(&g_done_count, 1u);
        s_is_last = (prev == NBLK - 1);
    }
    __syncthreads();

    // ---- Last block: deterministic final sum + counter reset ----
    if (s_is_last) {
        __threadfence();
        float a = 0.0f;
        for (int k = tid; k < NBLK; k += TPB)
            a += g_partials[k];
#pragma unroll
        for (int o = 16; o > 0; o >>= 1)
            a += __shfl_xor_sync(0xffffffffu, a, o);
        if ((tid & 31) == 0) s_red[tid >> 5] = a;
        __syncthreads();
        if (tid == 0) {
            float total = 0.0f;
#pragma unroll
            for (int w = 0; w < WARPS_PB; ++w) total += s_red[w];
            out[0] = total * (1.0f / (float)B_TOTAL);
            g_done_count = 0;   // reset for next graph replay
        }
    }
}

extern "C" void kernel_launch(void* const* d_in, const int* in_sizes, int n_in,
                              void* d_out, int out_size)
{
    const float* pred = (const float*)d_in[0];
    const int*   lab  = (const int*)d_in[1];
    float*       out  = (float*)d_out;

    ce_lsr_warp_pipe_kernel<<<NBLK, TPB>>>(pred, lab, out);
}

// round 7
// speedup vs baseline: 1.0018x; 1.0018x over previous
#include <cuda_runtime.h>
#include <cuda_bf16.h>
#include <cstdint>

// Problem constants: B=2097152, C=3, T=5
#define B_TOTAL     2097152
#define TPB         256
#define TILE_B      256                       // 1 b per thread per tile
#define NTILES      (B_TOTAL / TILE_B)        // 8192
#define GRID        740                       // 5 blocks x 148 SMs, persistent
#define PRED_W      (TILE_B * 15)             // floats per tile
#define LAB_W       (TILE_B * 5)              // ints per tile
#define PRED_BYTES  (PRED_W * 4)              // 15360
#define LAB_BYTES   (LAB_W * 4)               // 5120
#define TILE_BYTES  (PRED_BYTES + LAB_BYTES)  // 20480

#define FILLUP      (-100)
#define BASE_P      (0.2f / 3.0f)             // SMOOTHING / C
#define ONE_MS      0.8f                      // 1 - SMOOTHING

__device__ float        g_partials[GRID];
__device__ unsigned int g_done_count = 0;

__device__ __forceinline__ uint32_t smem_u32(const void* p)
{
    return (uint32_t)__cvta_generic_to_shared(p);
}

__device__ __forceinline__ void mbar_init(uint32_t mbar, uint32_t count)
{
    asm volatile("mbarrier.init.shared.b64 [%0], %1;" :: "r"(mbar), "r"(count) : "memory");
}

__device__ __forceinline__ void mbar_wait(uint32_t mbar, int parity)
{
    asm volatile(
        "{\n\t"
        ".reg .pred P;\n\t"
        "WAIT_%=:\n\t"
        "mbarrier.try_wait.parity.acquire.cta.shared::cta.b64 P, [%0], %1, 0x989680;\n\t"
        "@P bra.uni DONE_%=;\n\t"
        "bra.uni WAIT_%=;\n\t"
        "DONE_%=:\n\t"
        "}"
        :: "r"(mbar), "r"(parity) : "memory");
}

// One elected thread: expect full tile bytes, then two 1D bulk copies (TMA path).
__device__ __forceinline__ void issue_tile(uint32_t mbar, uint32_t sp, uint32_t sl,
                                           const float* __restrict__ gp,
                                           const int* __restrict__ gl)
{
    asm volatile("mbarrier.arrive.expect_tx.shared.b64 _, [%0], %1;"
                 :: "r"(mbar), "r"((uint32_t)TILE_BYTES) : "memory");
    asm volatile("cp.async.bulk.shared::cta.global.mbarrier::complete_tx::bytes [%0], [%1], %2, [%3];"
                 :: "r"(sp), "l"(gp), "r"((uint32_t)PRED_BYTES), "r"(mbar) : "memory");
    asm volatile("cp.async.bulk.shared::cta.global.mbarrier::complete_tx::bytes [%0], [%1], %2, [%3];"
                 :: "r"(sl), "l"(gl), "r"((uint32_t)LAB_BYTES), "r"(mbar) : "memory");
}

__global__ __launch_bounds__(TPB, 5)
void ce_lsr_tma_kernel(const float* __restrict__ pred,
                       const int* __restrict__ lab,
                       float* __restrict__ out)
{
    __shared__ alignas(16) float s_pred[2][PRED_W];   // 2 x 15 KB
    __shared__ alignas(16) int   s_lab[2][LAB_W];     // 2 x 5 KB
    __shared__ alignas(8) unsigned long long s_mbar[2];
    __shared__ float s_red[TPB / 32];
    __shared__ bool  s_is_last;

    const int tid = threadIdx.x;
    const int bid = blockIdx.x;

    const uint32_t mb0 = smem_u32(&s_mbar[0]);
    const uint32_t mb1 = smem_u32(&s_mbar[1]);
    const uint32_t sp0 = smem_u32(s_pred[0]);
    const uint32_t sp1 = smem_u32(s_pred[1]);
    const uint32_t sl0 = smem_u32(s_lab[0]);
    const uint32_t sl1 = smem_u32(s_lab[1]);

    // Number of tiles for this block (grid-stride: bid, bid+GRID, ...)
    const int n = (NTILES - 1 - bid) / GRID + 1;

    if (tid == 0) {
        mbar_init(mb0, 1);
        mbar_init(mb1, 1);
    }
    __syncthreads();

    if (tid == 0) {
        long t0 = bid;
        issue_tile(mb0, sp0, sl0, pred + t0 * PRED_W, lab + t0 * LAB_W);
        long t1 = bid + GRID;
        if (n > 1)
            issue_tile(mb1, sp1, sl1, pred + t1 * PRED_W, lab + t1 * LAB_W);
    }

    float acc = 0.0f;
    int ph0 = 0, ph1 = 0;

    for (int k = 0; k < n; ++k) {
        const int s = k & 1;
        if (s == 0) { mbar_wait(mb0, ph0); ph0 ^= 1; }
        else        { mbar_wait(mb1, ph1); ph1 ^= 1; }

        // Word strides 15 / 5 coprime with 32 -> bank-conflict-free scalar LDS
        const float* x  = s_pred[s] + tid * 15;   // [c*5 + t]
        const int*   lb = s_lab[s] + tid * 5;
#pragma unroll
        for (int t = 0; t < 5; ++t) {
            float x0 = x[t], x1 = x[5 + t], x2 = x[10 + t];
            int   l  = lb[t];

            // x0 cancels: loss = log(1+e^d1+e^d2) - BASE_P*(d1+d2) - 0.8*d_label
            float d1 = x1 - x0, d2 = x2 - x0;
            float e  = 1.0f + __expf(d1) + __expf(d2);
            float lg = __logf(e);

            float dl = (l == 1) ? d1 : ((l == 2) ? d2 : 0.0f);
            float term = lg - BASE_P * (d1 + d2) - ONE_MS * dl;
            if (l != FILLUP) acc += term;
        }
        __syncthreads();    // all threads done reading stage s

        if (tid == 0 && k + 2 < n) {
            long tn = bid + (long)(k + 2) * GRID;
            issue_tile(s ? mb1 : mb0, s ? sp1 : sp0, s ? sl1 : sl0,
                       pred + tn * PRED_W, lab + tn * LAB_W);
        }
    }

    // ---- Deterministic reduction: warp -> block ----
#pragma unroll
    for (int o = 16; o > 0; o >>= 1)
        acc += __shfl_xor_sync(0xffffffffu, acc, o);
    if ((tid & 31) == 0) s_red[tid >> 5] = acc;
    __syncthreads();

    if (tid == 0) {
        float p = 0.0f;
#pragma unroll
        for (int w = 0; w < TPB / 32; ++w) p += s_red[w];
        g_partials[bid] = p;
        __threadfence();
        unsigned int prev = atomicAdd(&g_done_count, 1u);
        s_is_last = (prev == GRID - 1);
    }
    __syncthreads();

    // ---- Last block: deterministic final sum + counter reset ----
    if (s_is_last) {
        __threadfence();
        float a = 0.0f;
        for (int k = tid; k < GRID; k += TPB)
            a += g_partials[k];
#pragma unroll
        for (int o = 16; o > 0; o >>= 1)
            a += __shfl_xor_sync(0xffffffffu, a, o);
        if ((tid & 31) == 0) s_red[tid >> 5] = a;
        __syncthreads();
        if (tid == 0) {
            float total = 0.0f;
#pragma unroll
            for (int w = 0; w < TPB / 32; ++w) total += s_red[w];
            out[0] = total * (1.0f / (float)B_TOTAL);
            g_done_count = 0;   // reset for next graph replay
        }
    }
}

extern "C" void kernel_launch(void* const* d_in, const int* in_sizes, int n_in,
                              void* d_out, int out_size)
{
    const float* pred = (const float*)d_in[0];
    const int*   lab  = (const int*)d_in[1];
    float*       out  = (float*)d_out;

    ce_lsr_tma_kernel<<<GRID, TPB>>>(pred, lab, out);
}